// round 1
// baseline (speedup 1.0000x reference)
#include <cuda_runtime.h>

#define W_   128
#define H_   256
#define D_   256
#define HW_  32768            // H_*W_ ... careful: stride along D axis = H_*W_? No: layout (B,D,H,W): stride_d = H_*W_
#define NVOX 16777216         // 2*256*256*128
#define NVEC 4194304          // NVOX/4
#define LAMB 0.01f

// Persistent dual-variable scratch (alloc-free rule: __device__ globals).
__device__ float g_p[NVOX];
__device__ float g_q[NVOX];
__device__ float g_s[NVOX];

__device__ __forceinline__ float zf(float t, float s) {
    // z = t - LAMB*(t - sino)
    return t - LAMB * (t - s);
}
__device__ __forceinline__ float clip(float x, float sg) {
    return fminf(fmaxf(x, -sg), sg);
}
__device__ __forceinline__ float4 zf4(float4 t, float4 s) {
    float4 z;
    z.x = zf(t.x, s.x); z.y = zf(t.y, s.y);
    z.z = zf(t.z, s.z); z.w = zf(t.w, s.w);
    return z;
}

// Kernel 1: dual update. Reads t,sino (+ forward halos), old p,q,s (unless FIRST),
// writes extrapolated p,q,s. If FIRST, also writes the image copy to out0.
template <bool FIRST>
__global__ __launch_bounds__(256)
void dtv_dual(const float* __restrict__ t, const float* __restrict__ sino,
              const float* __restrict__ sig, const float* __restrict__ ntp,
              int cascade, float* __restrict__ out0)
{
    int v = blockIdx.x * 256 + threadIdx.x;
    if (v >= NVEC) return;
    int idx = v << 2;                       // element index, multiple of 4
    int w = idx & (W_ - 1);                 // 0..124 (first element of the vec)
    int h = (idx >> 7) & (H_ - 1);
    int d = (idx >> 15) & (D_ - 1);

    const int strideD = H_ * W_;            // 32768

    float4 t4 = *(const float4*)(t + idx);
    float4 s4 = *(const float4*)(sino + idx);
    float4 z  = zf4(t4, s4);

    // neighbor z along D (axis 1)
    float4 zd = z;
    if (d < D_ - 1) {
        float4 tn = *(const float4*)(t + idx + strideD);
        float4 sn = *(const float4*)(sino + idx + strideD);
        zd = zf4(tn, sn);
    }
    // neighbor z along H (axis 2)
    float4 zh = z;
    if (h < H_ - 1) {
        float4 tn = *(const float4*)(t + idx + W_);
        float4 sn = *(const float4*)(sino + idx + W_);
        zh = zf4(tn, sn);
    }
    // neighbor z along W (axis 3): shift within vector; element 3 needs idx+4
    float zw3 = z.w;
    if (w < W_ - 4) zw3 = zf(__ldg(t + idx + 4), __ldg(sino + idx + 4));

    // fwd_diff = z_next - z  (0 at last index, achieved by z_next = z)
    float4 dp, dq, ds;
    dp.x = zd.x - z.x; dp.y = zd.y - z.y; dp.z = zd.z - z.z; dp.w = zd.w - z.w;
    dq.x = zh.x - z.x; dq.y = zh.y - z.y; dq.z = zh.z - z.z; dq.w = zh.w - z.w;
    ds.x = z.y - z.x;  ds.y = z.z - z.y;  ds.z = z.w - z.z;  ds.w = zw3 - z.w;

    float sg0 = __ldg(sig + 0), sg1 = __ldg(sig + 1), sg2 = __ldg(sig + 2);
    float nt  = __ldg(ntp + cascade);

    float4 p0, q0, s0;
    if (FIRST) {
        p0 = make_float4(0.f, 0.f, 0.f, 0.f);
        q0 = p0; s0 = p0;
    } else {
        p0 = *(const float4*)(g_p + idx);
        q0 = *(const float4*)(g_q + idx);
        s0 = *(const float4*)(g_s + idx);
    }

    float4 pe, qe, se;
    {
        float pn;
        pn = clip(p0.x - dp.x, sg0); pe.x = pn + nt * (pn - p0.x);
        pn = clip(p0.y - dp.y, sg0); pe.y = pn + nt * (pn - p0.y);
        pn = clip(p0.z - dp.z, sg0); pe.z = pn + nt * (pn - p0.z);
        pn = clip(p0.w - dp.w, sg0); pe.w = pn + nt * (pn - p0.w);
        pn = clip(q0.x - dq.x, sg1); qe.x = pn + nt * (pn - q0.x);
        pn = clip(q0.y - dq.y, sg1); qe.y = pn + nt * (pn - q0.y);
        pn = clip(q0.z - dq.z, sg1); qe.z = pn + nt * (pn - q0.z);
        pn = clip(q0.w - dq.w, sg1); qe.w = pn + nt * (pn - q0.w);
        pn = clip(s0.x - ds.x, sg2); se.x = pn + nt * (pn - s0.x);
        pn = clip(s0.y - ds.y, sg2); se.y = pn + nt * (pn - s0.y);
        pn = clip(s0.z - ds.z, sg2); se.z = pn + nt * (pn - s0.z);
        pn = clip(s0.w - ds.w, sg2); se.w = pn + nt * (pn - s0.w);
    }

    *(float4*)(g_p + idx) = pe;
    *(float4*)(g_q + idx) = qe;
    *(float4*)(g_s + idx) = se;

    if (FIRST) {
        // out slice 0 = image (we already hold it)
        *(float4*)(out0 + idx) = t4;
    }
}

// Kernel 2: primal update. t_out = divT(p) + divT(q) + divT(s) + clip(z, sig3)
// fwd_diff_t(p)[j] = (j>0 ? p[j-1] : 0) - (j<N-1 ? p[j] : 0)
__global__ __launch_bounds__(256)
void dtv_primal(const float* __restrict__ t, const float* __restrict__ sino,
                const float* __restrict__ sig, float* __restrict__ tout)
{
    int v = blockIdx.x * 256 + threadIdx.x;
    if (v >= NVEC) return;
    int idx = v << 2;
    int w = idx & (W_ - 1);
    int h = (idx >> 7) & (H_ - 1);
    int d = (idx >> 15) & (D_ - 1);

    const int strideD = H_ * W_;

    float4 pv = *(const float4*)(g_p + idx);
    float4 qv = *(const float4*)(g_q + idx);
    float4 sv = *(const float4*)(g_s + idx);

    float4 pd = make_float4(0.f, 0.f, 0.f, 0.f);
    if (d > 0) pd = *(const float4*)(g_p + idx - strideD);
    float4 qh = make_float4(0.f, 0.f, 0.f, 0.f);
    if (h > 0) qh = *(const float4*)(g_q + idx - W_);
    float sl = (w > 0) ? __ldg(g_s + idx - 1) : 0.f;

    float4 t4 = *(const float4*)(t + idx);
    float4 s4 = *(const float4*)(sino + idx);
    float4 z  = zf4(t4, s4);
    float sg3 = __ldg(sig + 3);

    bool dlast = (d == D_ - 1);
    bool hlast = (h == H_ - 1);
    float pbx = dlast ? 0.f : pv.x, pby = dlast ? 0.f : pv.y,
          pbz = dlast ? 0.f : pv.z, pbw = dlast ? 0.f : pv.w;
    float qbx = hlast ? 0.f : qv.x, qby = hlast ? 0.f : qv.y,
          qbz = hlast ? 0.f : qv.z, qbw = hlast ? 0.f : qv.w;
    // W axis: elements are w..w+3; only element 3 can be W-1 (when w==124);
    // only element 0 can be 0 (when w==0).
    float sbx = sv.x, sby = sv.y, sbz = sv.z;
    float sbw = (w == W_ - 4) ? 0.f : sv.w;

    float4 o;
    o.x = pd.x - pbx + qh.x - qbx + sl   - sbx + clip(z.x, sg3);
    o.y = pd.y - pby + qh.y - qby + sv.x - sby + clip(z.y, sg3);
    o.z = pd.z - pbz + qh.z - qbz + sv.y - sbz + clip(z.z, sg3);
    o.w = pd.w - pbw + qh.w - qbw + sv.z - sbw + clip(z.w, sg3);

    *(float4*)(tout + idx) = o;
}

extern "C" void kernel_launch(void* const* d_in, const int* in_sizes, int n_in,
                              void* d_out, int out_size)
{
    // Defensive input mapping: two big fp32 volumes (image, sino in order),
    // one size-4 (sigma), one size-3 (nt).
    const float* image = nullptr;
    const float* sino  = nullptr;
    const float* sigma = nullptr;
    const float* ntv   = nullptr;
    for (int i = 0; i < n_in; i++) {
        if (in_sizes[i] == 4) sigma = (const float*)d_in[i];
        else if (in_sizes[i] == 3) ntv = (const float*)d_in[i];
        else if (!image) image = (const float*)d_in[i];
        else if (!sino)  sino  = (const float*)d_in[i];
    }
    float* out = (float*)d_out;

    dim3 grid(NVEC / 256), block(256);

    // cascade 0 (p=q=s=0 specialization; also writes out slice 0 = image)
    dtv_dual<true ><<<grid, block>>>(image, sino, sigma, ntv, 0, out);
    dtv_primal     <<<grid, block>>>(image, sino, sigma, out + 1u * NVOX);
    // cascade 1
    dtv_dual<false><<<grid, block>>>(out + 1u * NVOX, sino, sigma, ntv, 1, nullptr);
    dtv_primal     <<<grid, block>>>(out + 1u * NVOX, sino, sigma, out + 2u * NVOX);
    // cascade 2
    dtv_dual<false><<<grid, block>>>(out + 2u * NVOX, sino, sigma, ntv, 2, nullptr);
    dtv_primal     <<<grid, block>>>(out + 2u * NVOX, sino, sigma, out + 3u * NVOX);
}

// round 3
// speedup vs baseline: 1.4887x; 1.4887x over previous
#include <cuda_runtime.h>

#define W_   128
#define H_   256
#define D_   256
#define NVOX 16777216         // 2*256*256*128
#define NVEC 4194304          // NVOX/4
#define SD_  32768            // stride along D = H_*W_
#define LAMB 0.01f

// Persistent dual-variable scratch, DOUBLE-BUFFERED to avoid the intra-kernel
// read/write race on neighbor cells (alloc-free rule: __device__ globals).
__device__ float g_p0[NVOX]; __device__ float g_p1[NVOX];
__device__ float g_q0[NVOX]; __device__ float g_q1[NVOX];
__device__ float g_s0[NVOX]; __device__ float g_s1[NVOX];

__device__ __forceinline__ float4 ld4(const float* p) { return *(const float4*)p; }

__device__ __forceinline__ float zf(float t, float s) { return t - LAMB * (t - s); }
__device__ __forceinline__ float clip(float x, float sg) { return fminf(fmaxf(x, -sg), sg); }
__device__ __forceinline__ float4 zf4(float4 t, float4 s) {
    float4 z;
    z.x = zf(t.x, s.x); z.y = zf(t.y, s.y);
    z.z = zf(t.z, s.z); z.w = zf(t.w, s.w);
    return z;
}
// extrapolated dual update: pn = clip(p0 - dz, sg); pe = pn + nt*(pn - p0)
__device__ __forceinline__ float dualu(float p0, float dz, float sg, float nt) {
    float pn = clip(p0 - dz, sg);
    return pn + nt * (pn - p0);
}
__device__ __forceinline__ float4 dualu4(float4 p0, float4 dz, float sg, float nt) {
    float4 r;
    r.x = dualu(p0.x, dz.x, sg, nt);
    r.y = dualu(p0.y, dz.y, sg, nt);
    r.z = dualu(p0.z, dz.z, sg, nt);
    r.w = dualu(p0.w, dz.w, sg, nt);
    return r;
}

// Fused cascade: computes extrapolated duals at x and x-1 (per axis) from z,
// stores new duals into the WRITE buffer (unless LAST) and t_out directly.
// Old duals come from the READ buffer — disjoint, so no race.
template <bool FIRST, bool LAST>
__global__ __launch_bounds__(256)
void dtv_fused(const float* __restrict__ t, const float* __restrict__ sino,
               const float* __restrict__ sig, const float* __restrict__ ntp,
               int cascade,
               const float* __restrict__ rp, const float* __restrict__ rq,
               const float* __restrict__ rs,
               float* __restrict__ wp, float* __restrict__ wq,
               float* __restrict__ ws,
               float* __restrict__ tout, float* __restrict__ out0)
{
    int v = blockIdx.x * 256 + threadIdx.x;
    if (v >= NVEC) return;
    int idx = v << 2;                 // element index (multiple of 4)
    int w = idx & (W_ - 1);           // w0 of the vec: 0,4,...,124
    int h = (idx >> 7) & (H_ - 1);
    int d = (idx >> 15) & (D_ - 1);

    float4 t4 = ld4(t + idx);
    float4 s4 = ld4(sino + idx);
    float4 z  = zf4(t4, s4);

    bool dhi = (d < D_ - 1), dlo = (d > 0);
    bool hhi = (h < H_ - 1), hlo = (h > 0);

    float4 zdp = z;                   // z(x+e_d); ==z => dz=0 at boundary
    if (dhi) zdp = zf4(ld4(t + idx + SD_), ld4(sino + idx + SD_));
    float4 zdm = z;
    if (dlo) zdm = zf4(ld4(t + idx - SD_), ld4(sino + idx - SD_));

    float4 zhp = z;
    if (hhi) zhp = zf4(ld4(t + idx + W_), ld4(sino + idx + W_));
    float4 zhm = z;
    if (hlo) zhm = zf4(ld4(t + idx - W_), ld4(sino + idx - W_));

    float zm1 = 0.f;
    if (w > 0) zm1 = zf(__ldg(t + idx - 1), __ldg(sino + idx - 1));
    float zp4 = z.w;                  // => dzw lane3 = 0 at w0==124
    if (w < W_ - 4) zp4 = zf(__ldg(t + idx + 4), __ldg(sino + idx + 4));

    float sg0 = __ldg(sig + 0), sg1 = __ldg(sig + 1);
    float sg2 = __ldg(sig + 2), sg3 = __ldg(sig + 3);
    float nt  = __ldg(ntp + cascade);

    // old duals (at x, and at backward neighbor per axis) — from READ buffer
    float4 p0, q0, s0, p0m, q0m;
    float  s0m;
    if (FIRST) {
        p0 = q0 = s0 = p0m = q0m = make_float4(0.f, 0.f, 0.f, 0.f);
        s0m = 0.f;
    } else {
        p0 = ld4(rp + idx);
        q0 = ld4(rq + idx);
        s0 = ld4(rs + idx);
        p0m = dlo ? ld4(rp + idx - SD_) : make_float4(0.f, 0.f, 0.f, 0.f);
        q0m = hlo ? ld4(rq + idx - W_)  : make_float4(0.f, 0.f, 0.f, 0.f);
        s0m = (w > 0) ? __ldg(rs + idx - 1) : 0.f;
    }

    // ---- D axis duals ----
    float4 dz;
    dz.x = zdp.x - z.x; dz.y = zdp.y - z.y; dz.z = zdp.z - z.z; dz.w = zdp.w - z.w;
    float4 pe = dualu4(p0, dz, sg0, nt);            // dual at x (stored)
    dz.x = z.x - zdm.x; dz.y = z.y - zdm.y; dz.z = z.z - zdm.z; dz.w = z.w - zdm.w;
    float4 pem = dualu4(p0m, dz, sg0, nt);          // dual at x - e_d (if dlo)

    // ---- H axis duals ----
    dz.x = zhp.x - z.x; dz.y = zhp.y - z.y; dz.z = zhp.z - z.z; dz.w = zhp.w - z.w;
    float4 qe = dualu4(q0, dz, sg1, nt);
    dz.x = z.x - zhm.x; dz.y = z.y - zhm.y; dz.z = z.z - zhm.z; dz.w = z.w - zhm.w;
    float4 qem = dualu4(q0m, dz, sg1, nt);

    // ---- W axis duals (within vector) ----
    float4 dzw;
    dzw.x = z.y - z.x; dzw.y = z.z - z.y; dzw.z = z.w - z.z; dzw.w = zp4 - z.w;
    float4 se = dualu4(s0, dzw, sg2, nt);
    float sem = dualu(s0m, z.x - zm1, sg2, nt);     // dual at (w0-1), if w>0

    // ---- primal (divergence via adjoint stencils) ----
    float dm = dhi ? 1.f : 0.f;       // subtract pe only if d < D-1
    float hm = hhi ? 1.f : 0.f;
    float Adx = (dlo ? pem.x : 0.f) - dm * pe.x;
    float Ady = (dlo ? pem.y : 0.f) - dm * pe.y;
    float Adz = (dlo ? pem.z : 0.f) - dm * pe.z;
    float Adw = (dlo ? pem.w : 0.f) - dm * pe.w;

    float Ahx = (hlo ? qem.x : 0.f) - hm * qe.x;
    float Ahy = (hlo ? qem.y : 0.f) - hm * qe.y;
    float Ahz = (hlo ? qem.z : 0.f) - hm * qe.z;
    float Ahw = (hlo ? qem.w : 0.f) - hm * qe.w;

    float wm3 = (w < W_ - 4) ? 1.f : 0.f;           // lane3 is w=127 iff w0==124
    float Awx = ((w > 0) ? sem : 0.f) - se.x;
    float Awy = se.x - se.y;
    float Awz = se.y - se.z;
    float Aww = se.z - wm3 * se.w;

    float4 o;
    o.x = Adx + Ahx + Awx + clip(z.x, sg3);
    o.y = Ady + Ahy + Awy + clip(z.y, sg3);
    o.z = Adz + Ahz + Awz + clip(z.z, sg3);
    o.w = Adw + Ahw + Aww + clip(z.w, sg3);

    *(float4*)(tout + idx) = o;
    if (!LAST) {
        *(float4*)(wp + idx) = pe;
        *(float4*)(wq + idx) = qe;
        *(float4*)(ws + idx) = se;
    }
    if (FIRST) {
        *(float4*)(out0 + idx) = t4;  // out slice 0 = image (free copy)
    }
}

extern "C" void kernel_launch(void* const* d_in, const int* in_sizes, int n_in,
                              void* d_out, int out_size)
{
    const float* image = nullptr;
    const float* sino  = nullptr;
    const float* sigma = nullptr;
    const float* ntv   = nullptr;
    for (int i = 0; i < n_in; i++) {
        if (in_sizes[i] == 4) sigma = (const float*)d_in[i];
        else if (in_sizes[i] == 3) ntv = (const float*)d_in[i];
        else if (!image) image = (const float*)d_in[i];
        else if (!sino)  sino  = (const float*)d_in[i];
    }
    float* out = (float*)d_out;

    // Resolve device-global scratch addresses on host.
    float *p0a, *p1a, *q0a, *q1a, *s0a, *s1a;
    cudaGetSymbolAddress((void**)&p0a, g_p0);
    cudaGetSymbolAddress((void**)&p1a, g_p1);
    cudaGetSymbolAddress((void**)&q0a, g_q0);
    cudaGetSymbolAddress((void**)&q1a, g_q1);
    cudaGetSymbolAddress((void**)&s0a, g_s0);
    cudaGetSymbolAddress((void**)&s1a, g_s1);

    dim3 grid(NVEC / 256), block(256);

    // cascade 0: writes buffer1, no reads
    dtv_fused<true , false><<<grid, block>>>(image, sino, sigma, ntv, 0,
        nullptr, nullptr, nullptr, p1a, q1a, s1a, out + 1u * NVOX, out);
    // cascade 1: reads buffer1, writes buffer0
    dtv_fused<false, false><<<grid, block>>>(out + 1u * NVOX, sino, sigma, ntv, 1,
        p1a, q1a, s1a, p0a, q0a, s0a, out + 2u * NVOX, nullptr);
    // cascade 2: reads buffer0, no dual stores (dead after t3)
    dtv_fused<false, true ><<<grid, block>>>(out + 2u * NVOX, sino, sigma, ntv, 2,
        p0a, q0a, s0a, nullptr, nullptr, nullptr, out + 3u * NVOX, nullptr);
}

// round 4
// speedup vs baseline: 1.6138x; 1.0840x over previous
#include <cuda_runtime.h>

#define W_   128
#define H_   256
#define D_   256
#define NVOX 16777216         // 2*256*256*128
#define NVEC 4194304          // NVOX/4
#define SD_  32768            // stride along D = H_*W_
#define LAMB 0.01f
#define FULLM 0xffffffffu

// Persistent scratch: double-buffered duals + two z buffers.
__device__ float g_p0[NVOX]; __device__ float g_p1[NVOX];
__device__ float g_q0[NVOX]; __device__ float g_q1[NVOX];
__device__ float g_s0[NVOX]; __device__ float g_s1[NVOX];
__device__ float g_z1[NVOX]; __device__ float g_z2[NVOX];

__device__ __forceinline__ float4 ld4(const float* p) { return *(const float4*)p; }

__device__ __forceinline__ float zf(float t, float s) { return t - LAMB * (t - s); }
__device__ __forceinline__ float clip(float x, float sg) { return fminf(fmaxf(x, -sg), sg); }
__device__ __forceinline__ float4 zf4(float4 t, float4 s) {
    float4 z;
    z.x = zf(t.x, s.x); z.y = zf(t.y, s.y);
    z.z = zf(t.z, s.z); z.w = zf(t.w, s.w);
    return z;
}
__device__ __forceinline__ float4 sub4(float4 a, float4 b) {
    float4 r; r.x = a.x-b.x; r.y = a.y-b.y; r.z = a.z-b.z; r.w = a.w-b.w; return r;
}
// extrapolated dual update: pn = clip(p0 - dz, sg); pe = pn + nt*(pn - p0)
__device__ __forceinline__ float dualu(float p0, float dz, float sg, float nt) {
    float pn = clip(p0 - dz, sg);
    return pn + nt * (pn - p0);
}
__device__ __forceinline__ float4 dualu4(float4 p0, float4 dz, float sg, float nt) {
    float4 r;
    r.x = dualu(p0.x, dz.x, sg, nt);
    r.y = dualu(p0.y, dz.y, sg, nt);
    r.z = dualu(p0.z, dz.z, sg, nt);
    r.w = dualu(p0.w, dz.w, sg, nt);
    return r;
}

// Shared tail: given z-stencil values + old duals, produce duals/primal.
// Returns primal output o; writes pe/qe/se through refs.
__device__ __forceinline__ float4 dtv_core(
    float4 z, float4 zdp, float4 zdm, float4 zhp, float4 zhm, float zp4,
    float4 p0, float4 q0, float4 s0, float4 p0m, float4 q0m,
    bool dhi, bool dlo, bool hhi, bool hlo, int lane,
    float sg0, float sg1, float sg2, float sg3, float nt,
    float4& pe, float4& qe, float4& se)
{
    // D axis duals (at x, and at x - e_d)
    pe = dualu4(p0, sub4(zdp, z), sg0, nt);
    float4 pem = dualu4(p0m, sub4(z, zdm), sg0, nt);
    // H axis duals
    qe = dualu4(q0, sub4(zhp, z), sg1, nt);
    float4 qem = dualu4(q0m, sub4(z, zhm), sg1, nt);
    // W axis duals (within vector + shuffle halo)
    float4 dzw;
    dzw.x = z.y - z.x; dzw.y = z.z - z.y; dzw.z = z.w - z.z; dzw.w = zp4 - z.w;
    se = dualu4(s0, dzw, sg2, nt);
    float sem = __shfl_up_sync(FULLM, se.w, 1);   // dual at w0-1, valid for lane>0

    // primal (divergence via adjoint stencils)
    float dm = dhi ? 1.f : 0.f;
    float hm = hhi ? 1.f : 0.f;
    float4 o;
    o.x = (dlo ? pem.x : 0.f) - dm * pe.x
        + (hlo ? qem.x : 0.f) - hm * qe.x
        + ((lane > 0) ? sem : 0.f) - se.x + clip(z.x, sg3);
    o.y = (dlo ? pem.y : 0.f) - dm * pe.y
        + (hlo ? qem.y : 0.f) - hm * qe.y
        + se.x - se.y + clip(z.y, sg3);
    o.z = (dlo ? pem.z : 0.f) - dm * pe.z
        + (hlo ? qem.z : 0.f) - hm * qe.z
        + se.y - se.z + clip(z.z, sg3);
    float wm3 = (lane < 31) ? 1.f : 0.f;
    o.w = (dlo ? pem.w : 0.f) - dm * pe.w
        + (hlo ? qem.w : 0.f) - hm * qe.w
        + se.z - wm3 * se.w + clip(z.w, sg3);
    return o;
}

// Cascade 0: duals start at 0; z computed from image,sino; also emits out0=image
// and z1 for the next cascade.
__global__ __launch_bounds__(256)
void dtv_c0(const float* __restrict__ image, const float* __restrict__ sino,
            const float* __restrict__ sig, const float* __restrict__ ntp,
            float* __restrict__ wp, float* __restrict__ wq, float* __restrict__ ws,
            float* __restrict__ wz, float* __restrict__ tout, float* __restrict__ out0)
{
    int v = blockIdx.x * 256 + threadIdx.x;
    int idx = v << 2;
    int lane = threadIdx.x & 31;
    int h = (idx >> 7) & (H_ - 1);
    int d = (idx >> 15) & (D_ - 1);
    bool dhi = (d < D_ - 1), dlo = (d > 0);
    bool hhi = (h < H_ - 1), hlo = (h > 0);

    float4 t4 = ld4(image + idx);
    float4 s4 = ld4(sino + idx);
    float4 z  = zf4(t4, s4);

    float4 zdp = dhi ? zf4(ld4(image + idx + SD_), ld4(sino + idx + SD_)) : z;
    float4 zdm = dlo ? zf4(ld4(image + idx - SD_), ld4(sino + idx - SD_)) : z;
    float4 zhp = hhi ? zf4(ld4(image + idx + W_),  ld4(sino + idx + W_))  : z;
    float4 zhm = hlo ? zf4(ld4(image + idx - W_),  ld4(sino + idx - W_))  : z;
    float zp4 = __shfl_down_sync(FULLM, z.x, 1);
    if (lane == 31) zp4 = z.w;         // boundary: dz=0

    float sg0 = __ldg(sig + 0), sg1 = __ldg(sig + 1);
    float sg2 = __ldg(sig + 2), sg3 = __ldg(sig + 3);
    float nt  = __ldg(ntp + 0);

    float4 zero = make_float4(0.f, 0.f, 0.f, 0.f);
    float4 pe, qe, se;
    float4 o = dtv_core(z, zdp, zdm, zhp, zhm, zp4,
                        zero, zero, zero, zero, zero,
                        dhi, dlo, hhi, hlo, lane,
                        sg0, sg1, sg2, sg3, nt, pe, qe, se);

    *(float4*)(tout + idx) = o;
    *(float4*)(out0 + idx) = t4;               // out slice 0 = image
    *(float4*)(wp + idx) = pe;
    *(float4*)(wq + idx) = qe;
    *(float4*)(ws + idx) = se;
    *(float4*)(wz + idx) = zf4(o, s4);         // z for cascade 1
}

// Cascades 1,2: z comes pre-materialized; duals from READ buffer; if !LAST also
// writes duals + z_next (needs sino at x for z_next).
template <bool LAST>
__global__ __launch_bounds__(256)
void dtv_next(const float* __restrict__ zin, const float* __restrict__ sino,
              const float* __restrict__ sig, const float* __restrict__ ntp, int cascade,
              const float* __restrict__ rp, const float* __restrict__ rq,
              const float* __restrict__ rs,
              float* __restrict__ wp, float* __restrict__ wq, float* __restrict__ ws,
              float* __restrict__ wz, float* __restrict__ tout)
{
    int v = blockIdx.x * 256 + threadIdx.x;
    int idx = v << 2;
    int lane = threadIdx.x & 31;
    int h = (idx >> 7) & (H_ - 1);
    int d = (idx >> 15) & (D_ - 1);
    bool dhi = (d < D_ - 1), dlo = (d > 0);
    bool hhi = (h < H_ - 1), hlo = (h > 0);

    float4 z = ld4(zin + idx);
    float4 zdp = dhi ? ld4(zin + idx + SD_) : z;
    float4 zdm = dlo ? ld4(zin + idx - SD_) : z;
    float4 zhp = hhi ? ld4(zin + idx + W_)  : z;
    float4 zhm = hlo ? ld4(zin + idx - W_)  : z;
    float zp4 = __shfl_down_sync(FULLM, z.x, 1);
    if (lane == 31) zp4 = z.w;

    float sg0 = __ldg(sig + 0), sg1 = __ldg(sig + 1);
    float sg2 = __ldg(sig + 2), sg3 = __ldg(sig + 3);
    float nt  = __ldg(ntp + cascade);

    float4 zero = make_float4(0.f, 0.f, 0.f, 0.f);
    float4 p0 = ld4(rp + idx);
    float4 q0 = ld4(rq + idx);
    float4 s0 = ld4(rs + idx);
    float4 p0m = dlo ? ld4(rp + idx - SD_) : zero;
    float4 q0m = hlo ? ld4(rq + idx - W_)  : zero;

    float4 pe, qe, se;
    float4 o = dtv_core(z, zdp, zdm, zhp, zhm, zp4,
                        p0, q0, s0, p0m, q0m,
                        dhi, dlo, hhi, hlo, lane,
                        sg0, sg1, sg2, sg3, nt, pe, qe, se);

    *(float4*)(tout + idx) = o;
    if (!LAST) {
        *(float4*)(wp + idx) = pe;
        *(float4*)(wq + idx) = qe;
        *(float4*)(ws + idx) = se;
        float4 s4 = ld4(sino + idx);
        *(float4*)(wz + idx) = zf4(o, s4);     // z for next cascade
    }
}

extern "C" void kernel_launch(void* const* d_in, const int* in_sizes, int n_in,
                              void* d_out, int out_size)
{
    const float* image = nullptr;
    const float* sino  = nullptr;
    const float* sigma = nullptr;
    const float* ntv   = nullptr;
    for (int i = 0; i < n_in; i++) {
        if (in_sizes[i] == 4) sigma = (const float*)d_in[i];
        else if (in_sizes[i] == 3) ntv = (const float*)d_in[i];
        else if (!image) image = (const float*)d_in[i];
        else if (!sino)  sino  = (const float*)d_in[i];
    }
    float* out = (float*)d_out;

    float *p0a, *p1a, *q0a, *q1a, *s0a, *s1a, *z1a, *z2a;
    cudaGetSymbolAddress((void**)&p0a, g_p0);
    cudaGetSymbolAddress((void**)&p1a, g_p1);
    cudaGetSymbolAddress((void**)&q0a, g_q0);
    cudaGetSymbolAddress((void**)&q1a, g_q1);
    cudaGetSymbolAddress((void**)&s0a, g_s0);
    cudaGetSymbolAddress((void**)&s1a, g_s1);
    cudaGetSymbolAddress((void**)&z1a, g_z1);
    cudaGetSymbolAddress((void**)&z2a, g_z2);

    dim3 grid(NVEC / 256), block(256);

    // cascade 0: duals=0, writes buf1 + z1, out0 + t1
    dtv_c0<<<grid, block>>>(image, sino, sigma, ntv,
                            p1a, q1a, s1a, z1a, out + 1u * NVOX, out);
    // cascade 1: reads z1 + buf1, writes buf0 + z2, t2
    dtv_next<false><<<grid, block>>>(z1a, sino, sigma, ntv, 1,
                                     p1a, q1a, s1a,
                                     p0a, q0a, s0a, z2a, out + 2u * NVOX);
    // cascade 2: reads z2 + buf0, writes t3 only
    dtv_next<true ><<<grid, block>>>(z2a, sino, sigma, ntv, 2,
                                     p0a, q0a, s0a,
                                     nullptr, nullptr, nullptr, nullptr,
                                     out + 3u * NVOX);
}

// round 5
// speedup vs baseline: 1.9811x; 1.2276x over previous
#include <cuda_runtime.h>

#define W_   128
#define H_   256
#define D_   256
#define NVOX 16777216         // 2*256*256*128
#define NVEC 4194304          // NVOX/4
#define SD_  32768            // stride along D = H_*W_
#define LAMB 0.01f
#define FULLM 0xffffffffu

// Persistent scratch: only the z fields (duals are recomputed on the fly).
__device__ float g_z0[NVOX];
__device__ float g_z1[NVOX];
__device__ float g_z2[NVOX];

__device__ __forceinline__ float4 ld4(const float* p) { return *(const float4*)p; }

__device__ __forceinline__ float zf(float t, float s) { return t - LAMB * (t - s); }
__device__ __forceinline__ float clip(float x, float sg) { return fminf(fmaxf(x, -sg), sg); }
__device__ __forceinline__ float4 zf4(float4 t, float4 s) {
    float4 z;
    z.x = zf(t.x, s.x); z.y = zf(t.y, s.y);
    z.z = zf(t.z, s.z); z.w = zf(t.w, s.w);
    return z;
}
__device__ __forceinline__ float4 sub4(float4 a, float4 b) {
    float4 r; r.x = a.x-b.x; r.y = a.y-b.y; r.z = a.z-b.z; r.w = a.w-b.w; return r;
}
// one dual stage: pn = clip(p - dz, sg); return pn + nt*(pn - p)
__device__ __forceinline__ float dualu(float p, float dz, float sg, float nt) {
    float pn = clip(p - dz, sg);
    return pn + nt * (pn - p);
}
__device__ __forceinline__ float4 dualu4(float4 p, float4 dz, float sg, float nt) {
    float4 r;
    r.x = dualu(p.x, dz.x, sg, nt);
    r.y = dualu(p.y, dz.y, sg, nt);
    r.z = dualu(p.z, dz.z, sg, nt);
    r.w = dualu(p.w, dz.w, sg, nt);
    return r;
}
// chain the dual through NS cascades starting from 0
template <int NS>
__device__ __forceinline__ float4 chain4(const float4* dz, float sg, const float* nt) {
    float4 p = make_float4(0.f, 0.f, 0.f, 0.f);
#pragma unroll
    for (int c = 0; c < NS; c++) p = dualu4(p, dz[c], sg, nt[c]);
    return p;
}

// ---------------- cascade 0 ----------------
// z0 computed from image,sino; 1-stage duals; writes out0, t1, z0, z1.
__global__ __launch_bounds__(256)
void dtv_c0(const float* __restrict__ image, const float* __restrict__ sino,
            const float* __restrict__ sig, const float* __restrict__ ntp,
            float* __restrict__ wz0, float* __restrict__ wz1,
            float* __restrict__ tout, float* __restrict__ out0)
{
    int v = blockIdx.x * 256 + threadIdx.x;
    int idx = v << 2;
    int lane = threadIdx.x & 31;
    int h = (idx >> 7) & (H_ - 1);
    int d = (idx >> 15) & (D_ - 1);
    bool dhi = (d < D_ - 1), dlo = (d > 0);
    bool hhi = (h < H_ - 1), hlo = (h > 0);

    float4 t4 = ld4(image + idx);
    float4 s4 = ld4(sino + idx);
    float4 z  = zf4(t4, s4);

    float4 zdp = dhi ? zf4(ld4(image + idx + SD_), ld4(sino + idx + SD_)) : z;
    float4 zdm = dlo ? zf4(ld4(image + idx - SD_), ld4(sino + idx - SD_)) : z;
    float4 zhp = hhi ? zf4(ld4(image + idx + W_),  ld4(sino + idx + W_))  : z;
    float4 zhm = hlo ? zf4(ld4(image + idx - W_),  ld4(sino + idx - W_))  : z;
    float zp4 = __shfl_down_sync(FULLM, z.x, 1);
    if (lane == 31) zp4 = z.w;

    float sg0 = __ldg(sig+0), sg1 = __ldg(sig+1), sg2 = __ldg(sig+2), sg3 = __ldg(sig+3);
    float nt0 = __ldg(ntp + 0);

    // D axis
    float4 dz0 = sub4(zdp, z);
    float4 pe  = dualu4(make_float4(0,0,0,0), dz0, sg0, nt0);
    dz0 = sub4(z, zdm);
    float4 pem = dualu4(make_float4(0,0,0,0), dz0, sg0, nt0);
    // H axis
    float4 dz1 = sub4(zhp, z);
    float4 qe  = dualu4(make_float4(0,0,0,0), dz1, sg1, nt0);
    dz1 = sub4(z, zhm);
    float4 qem = dualu4(make_float4(0,0,0,0), dz1, sg1, nt0);
    // W axis
    float4 dzw;
    dzw.x = z.y - z.x; dzw.y = z.z - z.y; dzw.z = z.w - z.z; dzw.w = zp4 - z.w;
    float4 se = dualu4(make_float4(0,0,0,0), dzw, sg2, nt0);
    float sem = __shfl_up_sync(FULLM, se.w, 1);

    float4 o;
    o.x = (dlo ? pem.x : 0.f) - pe.x + (hlo ? qem.x : 0.f) - qe.x
        + ((lane > 0) ? sem : 0.f) - se.x + clip(z.x, sg3);
    o.y = (dlo ? pem.y : 0.f) - pe.y + (hlo ? qem.y : 0.f) - qe.y
        + se.x - se.y + clip(z.y, sg3);
    o.z = (dlo ? pem.z : 0.f) - pe.z + (hlo ? qem.z : 0.f) - qe.z
        + se.y - se.z + clip(z.z, sg3);
    o.w = (dlo ? pem.w : 0.f) - pe.w + (hlo ? qem.w : 0.f) - qe.w
        + se.z - se.w + clip(z.w, sg3);

    *(float4*)(tout + idx) = o;
    *(float4*)(out0 + idx) = t4;
    *(float4*)(wz0 + idx)  = z;
    *(float4*)(wz1 + idx)  = zf4(o, s4);
}

// ---------------- cascades 1 & 2 ----------------
// NS = number of z fields (2 for c1, 3 for c2). Duals recomputed by chaining.
template <int NS, bool LAST>
__global__ __launch_bounds__(256)
void dtv_chain(const float* __restrict__ za, const float* __restrict__ zb,
               const float* __restrict__ zc, const float* __restrict__ sino,
               const float* __restrict__ sig, const float* __restrict__ ntp,
               float* __restrict__ wz, float* __restrict__ tout)
{
    int v = blockIdx.x * 256 + threadIdx.x;
    int idx = v << 2;
    int lane = threadIdx.x & 31;
    int h = (idx >> 7) & (H_ - 1);
    int d = (idx >> 15) & (D_ - 1);
    bool dhi = (d < D_ - 1), dlo = (d > 0);
    bool hhi = (h < H_ - 1), hlo = (h > 0);

    const float* zs[3] = { za, zb, zc };

    float sg0 = __ldg(sig+0), sg1 = __ldg(sig+1), sg2 = __ldg(sig+2), sg3 = __ldg(sig+3);
    float nt[3];
#pragma unroll
    for (int c = 0; c < NS; c++) nt[c] = __ldg(ntp + c);

    float4 z[NS];
#pragma unroll
    for (int c = 0; c < NS; c++) z[c] = ld4(zs[c] + idx);

    float4 o = make_float4(0.f, 0.f, 0.f, 0.f);

    // ---- D axis ----
    {
        float4 dzx[NS], dzm[NS];
#pragma unroll
        for (int c = 0; c < NS; c++) {
            float4 zdp = dhi ? ld4(zs[c] + idx + SD_) : z[c];
            float4 zdm = dlo ? ld4(zs[c] + idx - SD_) : z[c];
            dzx[c] = sub4(zdp, z[c]);
            dzm[c] = sub4(z[c], zdm);
        }
        float4 pe  = chain4<NS>(dzx, sg0, nt);
        float4 pem = chain4<NS>(dzm, sg0, nt);
        float lm = dlo ? 1.f : 0.f;
        o.x += lm * pem.x - pe.x;
        o.y += lm * pem.y - pe.y;
        o.z += lm * pem.z - pe.z;
        o.w += lm * pem.w - pe.w;
    }
    // ---- H axis ----
    {
        float4 dzx[NS], dzm[NS];
#pragma unroll
        for (int c = 0; c < NS; c++) {
            float4 zhp = hhi ? ld4(zs[c] + idx + W_) : z[c];
            float4 zhm = hlo ? ld4(zs[c] + idx - W_) : z[c];
            dzx[c] = sub4(zhp, z[c]);
            dzm[c] = sub4(z[c], zhm);
        }
        float4 qe  = chain4<NS>(dzx, sg1, nt);
        float4 qem = chain4<NS>(dzm, sg1, nt);
        float lm = hlo ? 1.f : 0.f;
        o.x += lm * qem.x - qe.x;
        o.y += lm * qem.y - qe.y;
        o.z += lm * qem.z - qe.z;
        o.w += lm * qem.w - qe.w;
    }
    // ---- W axis ----
    {
        float4 dzw[NS];
#pragma unroll
        for (int c = 0; c < NS; c++) {
            float zp4 = __shfl_down_sync(FULLM, z[c].x, 1);
            if (lane == 31) zp4 = z[c].w;
            dzw[c].x = z[c].y - z[c].x;
            dzw[c].y = z[c].z - z[c].y;
            dzw[c].z = z[c].w - z[c].z;
            dzw[c].w = zp4 - z[c].w;
        }
        float4 se = chain4<NS>(dzw, sg2, nt);
        float sem = __shfl_up_sync(FULLM, se.w, 1);
        o.x += ((lane > 0) ? sem : 0.f) - se.x;
        o.y += se.x - se.y;
        o.z += se.y - se.z;
        o.w += se.z - se.w;   // se.w == 0 at lane31 automatically
    }

    float4 zl = z[NS - 1];
    o.x += clip(zl.x, sg3);
    o.y += clip(zl.y, sg3);
    o.z += clip(zl.z, sg3);
    o.w += clip(zl.w, sg3);

    *(float4*)(tout + idx) = o;
    if (!LAST) {
        float4 s4 = ld4(sino + idx);
        *(float4*)(wz + idx) = zf4(o, s4);
    }
}

extern "C" void kernel_launch(void* const* d_in, const int* in_sizes, int n_in,
                              void* d_out, int out_size)
{
    const float* image = nullptr;
    const float* sino  = nullptr;
    const float* sigma = nullptr;
    const float* ntv   = nullptr;
    for (int i = 0; i < n_in; i++) {
        if (in_sizes[i] == 4) sigma = (const float*)d_in[i];
        else if (in_sizes[i] == 3) ntv = (const float*)d_in[i];
        else if (!image) image = (const float*)d_in[i];
        else if (!sino)  sino  = (const float*)d_in[i];
    }
    float* out = (float*)d_out;

    float *z0a, *z1a, *z2a;
    cudaGetSymbolAddress((void**)&z0a, g_z0);
    cudaGetSymbolAddress((void**)&z1a, g_z1);
    cudaGetSymbolAddress((void**)&z2a, g_z2);

    dim3 grid(NVEC / 256), block(256);

    // cascade 0: writes out0, t1, z0, z1
    dtv_c0<<<grid, block>>>(image, sino, sigma, ntv,
                            z0a, z1a, out + 1u * NVOX, out);
    // cascade 1: reads z0,z1; writes t2, z2
    dtv_chain<2, false><<<grid, block>>>(z0a, z1a, nullptr, sino, sigma, ntv,
                                         z2a, out + 2u * NVOX);
    // cascade 2: reads z0,z1,z2; writes t3
    dtv_chain<3, true ><<<grid, block>>>(z0a, z1a, z2a, nullptr, sigma, ntv,
                                         nullptr, out + 3u * NVOX);
}